// round 14
// baseline (speedup 1.0000x reference)
#include <cuda_runtime.h>
#include <cuda_fp16.h>
#include <mma.h>
#include <math.h>
#include <stdint.h>

using namespace nvcuda;
typedef unsigned int u32;

#define B 2
#define S 2048
#define D 512
#define H 8
#define DH 64
#define NB 10
#define PI_F 3.14159265358979323846f

// ---------------- scratch ----------------------------------------------------
__device__ float g_qp[B*S*D];
__device__ float g_kp[B*S*D];
__device__ float g_vp[B*S*D];
__device__ __half g_qph[B*S*D];                    // half qp, pre-scaled 0.125
__device__ __half g_kph[B*S*D];                    // half kp
__device__ __half g_vph[B*S*D];                    // half vp
__device__ float g_coef[NB*B*H*S];                 // [n][b][h][s], pre-scaled by 0.1/8
__device__ __half g_e[(size_t)B*H*S*S];            // exp(logit) in fp16 (134 MB)
__device__ float g_rowsum[B*H*S];                  // sum of exp per row
__device__ float g_attnv[B*S*D];                   // attn @ V, (b,s, h*64+d)
__device__ float g_wt[D*NB*H];                     // Wcoef transposed: [d][n*8+h]

__device__ __forceinline__ float to_tf32(float x) {
    asm("cvt.rna.tf32.f32 %0, %1;" : "=f"(x) : "f"(x));
    return x;
}
__device__ __forceinline__ u32 sptr(const void* p) {
    return (u32)__cvta_generic_to_shared(p);
}
__device__ __forceinline__ void ldsm4(u32& r0, u32& r1, u32& r2, u32& r3, u32 addr) {
    asm volatile("ldmatrix.sync.aligned.m8n8.x4.shared.b16 {%0,%1,%2,%3}, [%4];"
        : "=r"(r0), "=r"(r1), "=r"(r2), "=r"(r3) : "r"(addr));
}
__device__ __forceinline__ void ldsm4t(u32& r0, u32& r1, u32& r2, u32& r3, u32 addr) {
    asm volatile("ldmatrix.sync.aligned.m8n8.x4.trans.shared.b16 {%0,%1,%2,%3}, [%4];"
        : "=r"(r0), "=r"(r1), "=r"(r2), "=r"(r3) : "r"(addr));
}
__device__ __forceinline__ void mma16816(float* d, u32 a0, u32 a1, u32 a2,
                                         u32 a3, u32 b0, u32 b1) {
    asm volatile("mma.sync.aligned.m16n8k16.row.col.f32.f16.f16.f32 "
        "{%0,%1,%2,%3}, {%4,%5,%6,%7}, {%8,%9}, {%0,%1,%2,%3};"
        : "+f"(d[0]), "+f"(d[1]), "+f"(d[2]), "+f"(d[3])
        : "r"(a0), "r"(a1), "r"(a2), "r"(a3), "r"(b0), "r"(b1));
}

// ---------------- tf32 wmma GEMM body:  C = A(MxK) @ W(KxN) + bias ----------
#define GT_ALD 36
#define GT_WLD 68
__device__ __forceinline__ void gemm_body(
    const float* __restrict__ A, const float* __restrict__ W,
    const float* __restrict__ bias, float* __restrict__ C,
    int M, int N, int K, int bm, int bn)
{
    __shared__ float As[128*GT_ALD];   // [m][k] k-chunk 32
    __shared__ float Ws[32*GT_WLD];    // [k][n]
    __shared__ float Bt[16*GT_WLD];    // bias tile (rows identical)
    const int tid = threadIdx.x, w = tid >> 5;
    const int wm = (w >> 1) * 32, wn = (w & 1) * 32;

    for (int i = tid; i < 16*64; i += 256) {
        int r = i >> 6, c = i & 63;
        Bt[r*GT_WLD + c] = bias[bn + c];
    }
    __syncthreads();

    wmma::fragment<wmma::accumulator, 16,16,8, float> acc[2][2];
    #pragma unroll
    for (int i = 0; i < 2; i++)
        #pragma unroll
        for (int j = 0; j < 2; j++)
            wmma::load_matrix_sync(acc[i][j], Bt + wn + j*16, GT_WLD, wmma::mem_row_major);

    for (int k0 = 0; k0 < K; k0 += 32) {
        #pragma unroll
        for (int i = 0; i < 4; i++) {
            int id = i*256 + tid;
            int row = id >> 3, kc = (id & 7) * 4;
            float4 v = *(const float4*)&A[(size_t)(bm + row) * K + k0 + kc];
            v.x = to_tf32(v.x); v.y = to_tf32(v.y);
            v.z = to_tf32(v.z); v.w = to_tf32(v.w);
            *(float4*)&As[row*GT_ALD + kc] = v;
        }
        #pragma unroll
        for (int i = 0; i < 2; i++) {
            int id = i*256 + tid;
            int kr = id >> 4, nc = (id & 15) * 4;
            float4 v = *(const float4*)&W[(size_t)(k0 + kr) * N + bn + nc];
            v.x = to_tf32(v.x); v.y = to_tf32(v.y);
            v.z = to_tf32(v.z); v.w = to_tf32(v.w);
            *(float4*)&Ws[kr*GT_WLD + nc] = v;
        }
        __syncthreads();
        #pragma unroll
        for (int ks = 0; ks < 4; ks++) {
            wmma::fragment<wmma::matrix_a, 16,16,8, wmma::precision::tf32, wmma::row_major> a0, a1;
            wmma::load_matrix_sync(a0, As + wm*GT_ALD + ks*8, GT_ALD);
            wmma::load_matrix_sync(a1, As + (wm+16)*GT_ALD + ks*8, GT_ALD);
            wmma::fragment<wmma::matrix_b, 16,16,8, wmma::precision::tf32, wmma::row_major> b0, b1;
            wmma::load_matrix_sync(b0, Ws + (ks*8)*GT_WLD + wn, GT_WLD);
            wmma::load_matrix_sync(b1, Ws + (ks*8)*GT_WLD + wn + 16, GT_WLD);
            wmma::mma_sync(acc[0][0], a0, b0, acc[0][0]);
            wmma::mma_sync(acc[0][1], a0, b1, acc[0][1]);
            wmma::mma_sync(acc[1][0], a1, b0, acc[1][0]);
            wmma::mma_sync(acc[1][1], a1, b1, acc[1][1]);
        }
        __syncthreads();
    }
    #pragma unroll
    for (int i = 0; i < 2; i++)
        #pragma unroll
        for (int j = 0; j < 2; j++)
            wmma::store_matrix_sync(C + (size_t)(bm + wm + i*16) * N + bn + wn + j*16,
                                    acc[i][j], N, wmma::mem_row_major);
}

__global__ __launch_bounds__(256) void gemm_bias_tc(
    const float* __restrict__ A, const float* __restrict__ W,
    const float* __restrict__ bias, float* __restrict__ C, int M, int N, int K)
{
    gemm_body(A, W, bias, C, M, N, K, blockIdx.y * 128, blockIdx.x * 64);
}

// three projections in one launch; z selects (q,k,v)
__global__ __launch_bounds__(256) void gemm3_kernel(
    const float* q, const float* k, const float* v,
    const float* Wq, const float* Wk, const float* Wv,
    const float* bq, const float* bk, const float* bv)
{
    const float* A; const float* W; const float* bias; float* C;
    if (blockIdx.z == 0)      { A = q; W = Wq; bias = bq; C = g_qp; }
    else if (blockIdx.z == 1) { A = k; W = Wk; bias = bk; C = g_kp; }
    else                      { A = v; W = Wv; bias = bv; C = g_vp; }
    gemm_body(A, W, bias, C, B*S, D, D, blockIdx.y * 128, blockIdx.x * 64);
}

// ---------------- Wcoef transpose --------------------------------------------
__global__ void transw_kernel(const float* __restrict__ Wcoef)
{
    int i = blockIdx.x * 256 + threadIdx.x;          // 40960 total
    if (i < D*NB*H) {
        int n = i / (D*H), rem = i % (D*H);
        int d = rem / H, h = rem % H;
        g_wt[d*(NB*H) + n*H + h] = Wcoef[i];
    }
}

// ---------------- qp/kp/vp -> half copies (0.125 folded into q) ---------------
__global__ void qkvconv_kernel()
{
    int i = blockIdx.x * 256 + threadIdx.x;          // over float4s: B*S*D/4
    {
        float4 v = *(const float4*)&g_qp[i*4];
        __half2 h2[2];
        h2[0] = __floats2half2_rn(0.125f*v.x, 0.125f*v.y);
        h2[1] = __floats2half2_rn(0.125f*v.z, 0.125f*v.w);
        *(uint2*)&g_qph[i*4] = *(uint2*)h2;
    }
    {
        float4 v = *(const float4*)&g_kp[i*4];
        __half2 h2[2];
        h2[0] = __floats2half2_rn(v.x, v.y);
        h2[1] = __floats2half2_rn(v.z, v.w);
        *(uint2*)&g_kph[i*4] = *(uint2*)h2;
    }
    {
        float4 v = *(const float4*)&g_vp[i*4];
        __half2 h2[2];
        h2[0] = __floats2half2_rn(v.x, v.y);
        h2[1] = __floats2half2_rn(v.z, v.w);
        *(uint2*)&g_vph[i*4] = *(uint2*)h2;
    }
}

// ---------------- coef: (B*S x 512) @ (512 x 80) ------------------------------
__global__ void coef_kernel(const float* __restrict__ bcoef)
{
    __shared__ float qsm[16*33];
    __shared__ float wsm[32*80];
    const int bm = blockIdx.x * 16;
    const int t = threadIdx.x;
    const int r = t & 15;             // row within tile
    const int cg = t >> 4;            // col group: 5 cols each (16 groups)
    float acc[5] = {};
    for (int k0 = 0; k0 < D; k0 += 32) {
        #pragma unroll
        for (int i = 0; i < 2; i++) {
            int idx = i*256 + t;
            int rr = idx >> 5, cc = idx & 31;
            qsm[rr*33 + cc] = g_qp[(size_t)(bm + rr) * D + k0 + cc];
        }
        #pragma unroll
        for (int i = 0; i < 3; i++) {
            int idx = i*256 + t;
            if (idx < 640)
                *(float4*)&wsm[idx*4] = *(const float4*)&g_wt[k0*80 + idx*4];
        }
        __syncthreads();
        #pragma unroll 8
        for (int kk = 0; kk < 32; kk++) {
            float a = qsm[r*33 + kk];
            #pragma unroll
            for (int j = 0; j < 5; j++)
                acc[j] += a * wsm[kk*80 + cg*5 + j];
        }
        __syncthreads();
    }
    const int rg = bm + r;
    const int b = rg >> 11, s = rg & (S-1);
    #pragma unroll
    for (int j = 0; j < 5; j++) {
        int nh = cg*5 + j;
        int n = nh >> 3, h = nh & 7;
        float v = acc[j] + bcoef[nh];
        if (n == 1) v = fabsf(v);
        g_coef[(((size_t)n*B + b)*H + h)*S + s] = 0.0125f * v;   // 0.1 / sqrt(64)
    }
}

// ---------------- fused basis + QK^T + exp + rowsum, ALL HEADS per block -----
// One 64x64 (q,k) tile per block; sincos ladder computed ONCE, reused by 8 heads.
#define QK_LD 72
__global__ __launch_bounds__(256) void logits_kernel(const float* __restrict__ xdiff)
{
    __shared__ __half qs[64*QK_LD];
    __shared__ __half ks[64*QK_LD];

    const int k0 = blockIdx.x * 64, q0 = blockIdx.y * 64;
    const int b = blockIdx.z;
    const int tid = threadIdx.x;
    const int w = tid >> 5, lane = tid & 31;
    const int wr = w >> 1, wc = w & 1;        // 4x2 warps; warp tile 16q x 32k

    // thread's cells per mma C layout: rows qr, qr+8 ; col pairs kc0 + j*8
    const int qr  = wr*16 + (lane >> 2);
    const int kc0 = wc*32 + (lane & 3)*2;

    // ---- ladder, computed once (half2 over the 2 cols of each pair) ----
    half2 X[8], S1[8], C1[8], S3[8], C3[8], S5[8], C5[8], S9[8], C9[8];
    {
        const half2 hm4 = __float2half2_rn(-4.f);
        const half2 h2c = __float2half2_rn(2.f);
        #pragma unroll
        for (int jr = 0; jr < 2; jr++) {
            const float* xrow = &xdiff[((size_t)b*S + q0 + qr + jr*8) * S + k0];
            #pragma unroll
            for (int j = 0; j < 4; j++) {
                int idx = jr*4 + j;
                float2 x2 = *(const float2*)&xrow[kc0 + j*8];
                float t0 = fmaf(-2.f, rintf(0.5f * x2.x), x2.x);
                float t1 = fmaf(-2.f, rintf(0.5f * x2.y), x2.y);
                float s0f, c0f, s1f, c1f;
                __sincosf(PI_F * t0, &s0f, &c0f);
                __sincosf(PI_F * t1, &s1f, &c1f);
                half2 s1 = __floats2half2_rn(s0f, s1f);
                half2 c1 = __floats2half2_rn(c0f, c1f);
                half2 t2 = __hfma2(__hmul2(s1, s1), hm4, h2c);   // 2*cos(2 pi x)
                half2 s3 = __hfma2(t2, s1, s1);
                half2 c3 = __hfma2(t2, c1, __hneg2(c1));
                half2 s5 = __hfma2(t2, s3, __hneg2(s1));
                half2 c5 = __hfma2(t2, c3, __hneg2(c1));
                half2 s7 = __hfma2(t2, s5, __hneg2(s3));
                half2 c7 = __hfma2(t2, c5, __hneg2(c3));
                X[idx]  = __floats2half2_rn(x2.x, x2.y);
                S1[idx] = s1; C1[idx] = c1;
                S3[idx] = s3; C3[idx] = c3;
                S5[idx] = s5; C5[idx] = c5;
                S9[idx] = __hfma2(t2, s7, __hneg2(s5));
                C9[idx] = __hfma2(t2, c7, __hneg2(c5));
            }
        }
    }

    for (int h = 0; h < H; h++) {
        __syncthreads();   // previous head's ldsm reads complete
        for (int idx = tid; idx < 64*16; idx += 256) {
            int q = idx >> 4, c = (idx & 15) * 4;
            *(uint2*)&qs[q*QK_LD + c] =
                *(const uint2*)&g_qph[((size_t)b*S + q0 + q) * D + h*DH + c];
        }
        for (int idx = tid; idx < 64*16; idx += 256) {
            int k = idx >> 4, c = (idx & 15) * 4;
            *(uint2*)&ks[k*QK_LD + c] =
                *(const uint2*)&g_kph[((size_t)b*S + k0 + k) * D + h*DH + c];
        }

        // per-head 10-term dot from ladder registers -> c
        float c[4][4];
        #pragma unroll
        for (int jr = 0; jr < 2; jr++) {
            const int row = qr + jr*8;
            half2 ch[10];
            #pragma unroll
            for (int n = 0; n < NB; n++) {
                float cv = __ldg(&g_coef[(((size_t)n*B + b)*H + h)*S + q0 + row]);
                if (n == 1) cv = -0.5f * cv;
                ch[n] = __float2half2_rn(cv);
            }
            #pragma unroll
            for (int j = 0; j < 4; j++) {
                int idx = jr*4 + j;
                half2 a = __hmul2(ch[0], X[idx]);
                a = __hfma2(ch[1], __hmul2(X[idx], X[idx]), a);
                a = __hfma2(ch[2], S1[idx], a);  a = __hfma2(ch[3], C1[idx], a);
                a = __hfma2(ch[4], S3[idx], a);  a = __hfma2(ch[5], C3[idx], a);
                a = __hfma2(ch[6], S5[idx], a);  a = __hfma2(ch[7], C5[idx], a);
                a = __hfma2(ch[8], S9[idx], a);  a = __hfma2(ch[9], C9[idx], a);
                float2 f = __half22float2(a);
                c[j][jr*2 + 0] = f.x;
                c[j][jr*2 + 1] = f.y;
            }
        }
        __syncthreads();   // tiles loaded

        // mma: c += (0.125*Q) K^T
        #pragma unroll
        for (int kk = 0; kk < 4; kk++) {
            u32 a0, a1, a2, a3;
            ldsm4(a0, a1, a2, a3,
                  sptr(&qs[(wr*16 + (lane & 15))*QK_LD + kk*16 + (lane >> 4)*8]));
            #pragma unroll
            for (int jj = 0; jj < 2; jj++) {
                u32 b0, b1, b2, b3;
                ldsm4(b0, b1, b2, b3,
                      sptr(&ks[(wc*32 + jj*16 + (lane & 7) + ((lane >> 4) & 1)*8)*QK_LD
                               + kk*16 + ((lane >> 3) & 1)*8]));
                mma16816(c[jj*2],     a0, a1, a2, a3, b0, b1);
                mma16816(c[jj*2 + 1], a0, a1, a2, a3, b2, b3);
            }
        }

        // exp + row partial sums + e store (half2, quad-contiguous)
        float s0 = 0.f, s1 = 0.f;
        #pragma unroll
        for (int j = 0; j < 4; j++) {
            c[j][0] = __expf(c[j][0]); c[j][1] = __expf(c[j][1]);
            c[j][2] = __expf(c[j][2]); c[j][3] = __expf(c[j][3]);
            s0 += c[j][0] + c[j][1];
            s1 += c[j][2] + c[j][3];
        }
        s0 += __shfl_xor_sync(0xffffffffu, s0, 1);
        s0 += __shfl_xor_sync(0xffffffffu, s0, 2);
        s1 += __shfl_xor_sync(0xffffffffu, s1, 1);
        s1 += __shfl_xor_sync(0xffffffffu, s1, 2);
        const size_t rsb = (size_t)(b*H + h)*S + q0;
        if ((lane & 3) == 0) {
            atomicAdd(&g_rowsum[rsb + qr],     s0);
            atomicAdd(&g_rowsum[rsb + qr + 8], s1);
        }
        __half* e0 = &g_e[(rsb + qr) * S + k0];
        __half* e1 = &g_e[(rsb + qr + 8) * S + k0];
        #pragma unroll
        for (int j = 0; j < 4; j++) {
            *(__half2*)&e0[kc0 + j*8] = __floats2half2_rn(c[j][0], c[j][1]);
            *(__half2*)&e1[kc0 + j*8] = __floats2half2_rn(c[j][2], c[j][3]);
        }
    }
}

// ---------------- fused normalize + PV (PTX mma, smem-staged raw e) ----------
#define PT_LD 72
#define VT_LD 72
__global__ __launch_bounds__(256) void softpv_kernel(float* __restrict__ attn)
{
    __shared__ __half pt[64*PT_LD];
    __shared__ __half vt[64*VT_LD];
    const int b = blockIdx.z, h = blockIdx.y;
    const int q0 = blockIdx.x * 64;
    const int tid = threadIdx.x;
    const int w = tid >> 5, lane = tid & 31;
    const int wr = w >> 1, wc = w & 1;        // 4x2 warps: 16q x 32d each
    const int r  = tid >> 2, tq = tid & 3;    // attn write: 64 rows x 4 threads

    const size_t rowbase = ((size_t)(b*H + h)*S + q0) * S;
    float* arow = attn + rowbase + (size_t)r * S;
    const float riz_r = 1.f / g_rowsum[(size_t)(b*H + h)*S + q0 + r];

    const int qr = wr*16 + (lane >> 2);
    const float riz0 = 1.f / g_rowsum[(size_t)(b*H + h)*S + q0 + qr];
    const float riz1 = 1.f / g_rowsum[(size_t)(b*H + h)*S + q0 + qr + 8];

    float c[4][4] = {};

    for (int k0 = 0; k0 < S; k0 += 64) {
        // raw e tile (64q x 64k), straight half copy
        #pragma unroll
        for (int i = 0; i < 4; i++) {
            int idx = i*256 + tid;                    // uint2 (4 halves) units
            int row = idx >> 4, cc = (idx & 15) * 4;
            *(uint2*)&pt[row*PT_LD + cc] =
                *(const uint2*)&g_e[rowbase + (size_t)row * S + k0 + cc];
        }
        // V tile (64k x 64d)
        #pragma unroll
        for (int i = 0; i < 4; i++) {
            int idx = i*256 + tid;
            int k = idx >> 4, cc = (idx & 15) * 4;
            *(uint2*)&vt[k*VT_LD + cc] =
                *(const uint2*)&g_vph[((size_t)b*S + k0 + k)*D + h*DH + cc];
        }
        __syncthreads();
        // attn write from smem: e * riz
        #pragma unroll
        for (int j = 0; j < 4; j++) {
            __half2 e0 = *(const __half2*)&pt[r*PT_LD + tq*16 + j*4];
            __half2 e1 = *(const __half2*)&pt[r*PT_LD + tq*16 + j*4 + 2];
            float2 f0 = __half22float2(e0), f1 = __half22float2(e1);
            *(float4*)&arow[k0 + tq*16 + j*4] =
                make_float4(f0.x*riz_r, f0.y*riz_r, f1.x*riz_r, f1.y*riz_r);
        }
        // mma over 4 k-chunks of 16: A = raw e (ldsm), B = V^T (ldsm trans)
        #pragma unroll
        for (int kk = 0; kk < 4; kk++) {
            u32 a0, a1, a2, a3;
            ldsm4(a0, a1, a2, a3,
                  sptr(&pt[(wr*16 + (lane & 15))*PT_LD + kk*16 + (lane >> 4)*8]));
            #pragma unroll
            for (int jj = 0; jj < 2; jj++) {
                u32 b0, b1, b2, b3;
                ldsm4t(b0, b1, b2, b3,
                       sptr(&vt[(kk*16 + (lane & 15))*VT_LD + wc*32 + jj*16
                                + ((lane >> 4) << 3)]));
                mma16816(c[jj*2],     a0, a1, a2, a3, b0, b1);
                mma16816(c[jj*2 + 1], a0, a1, a2, a3, b2, b3);
            }
        }
        __syncthreads();
    }

    // scale by 1/rowsum and store
    #pragma unroll
    for (int j = 0; j < 4; j++) {
        int col = h*DH + wc*32 + j*8 + (lane & 3)*2;
        *(float2*)&g_attnv[((size_t)b*S + q0 + qr)*D + col] =
            make_float2(c[j][0]*riz0, c[j][1]*riz0);
        *(float2*)&g_attnv[((size_t)b*S + q0 + qr + 8)*D + col] =
            make_float2(c[j][2]*riz1, c[j][3]*riz1);
    }
}

// -----------------------------------------------------------------------------
extern "C" void kernel_launch(void* const* d_in, const int* in_sizes, int n_in,
                              void* d_out, int out_size)
{
    const float* q     = (const float*)d_in[0];
    const float* k     = (const float*)d_in[1];
    const float* v     = (const float*)d_in[2];
    const float* xdiff = (const float*)d_in[3];
    const float* Wq    = (const float*)d_in[4];
    const float* bq    = (const float*)d_in[5];
    const float* Wk    = (const float*)d_in[6];
    const float* bk    = (const float*)d_in[7];
    const float* Wv    = (const float*)d_in[8];
    const float* bv    = (const float*)d_in[9];
    const float* Wcoef = (const float*)d_in[10];
    const float* bcoef = (const float*)d_in[11];
    const float* Wo    = (const float*)d_in[12];
    const float* bo    = (const float*)d_in[13];
    float* out = (float*)d_out;                       // [B*S*D] out | [B*H*S*S] attn
    float* attn = out + (size_t)B*S*D;

    float *av, *rs;
    cudaGetSymbolAddress((void**)&av, g_attnv);
    cudaGetSymbolAddress((void**)&rs, g_rowsum);

    cudaMemsetAsync(rs, 0, (size_t)B*H*S*sizeof(float), 0);

    dim3 ggrid(D/64, (B*S)/128);
    gemm3_kernel<<<dim3(D/64, (B*S)/128, 3), 256>>>(q, k, v, Wq, Wk, Wv, bq, bk, bv);

    transw_kernel<<<(D*NB*H + 255)/256, 256>>>(Wcoef);
    qkvconv_kernel<<<(B*S*D/4)/256, 256>>>();
    coef_kernel<<<(B*S)/16, 256>>>(bcoef);

    logits_kernel<<<dim3(S/64, S/64, B), 256>>>(xdiff);

    softpv_kernel<<<dim3(S/64, H, B), 256>>>(attn);

    gemm_bias_tc<<<ggrid, 256>>>(av, Wo, bo, out, B*S, D, D);
}

// round 16
// speedup vs baseline: 1.1805x; 1.1805x over previous
#include <cuda_runtime.h>
#include <cuda_fp16.h>
#include <mma.h>
#include <math.h>
#include <stdint.h>

using namespace nvcuda;
typedef unsigned int u32;

#define B 2
#define S 2048
#define D 512
#define H 8
#define DH 64
#define NB 10
#define PI_F 3.14159265358979323846f

// ---------------- scratch ----------------------------------------------------
__device__ __half g_qph[B*S*D];                    // half qp, pre-scaled 0.125
__device__ __half g_kph[B*S*D];                    // half kp
__device__ __half g_vph[B*S*D];                    // half vp
__device__ float g_coef[NB*B*H*S];                 // [n][b][h][s], pre-scaled by 0.1/8
__device__ __half g_e[(size_t)B*H*S*S];            // exp(logit) in fp16 (134 MB)
__device__ float g_rowsum[B*H*S];                  // sum of exp per row
__device__ float g_attnv[B*S*D];                   // attn @ V, (b,s, h*64+d)
__device__ float g_wt[D*NB*H];                     // Wcoef transposed: [d][n*8+h]

__device__ __forceinline__ float to_tf32(float x) {
    asm("cvt.rna.tf32.f32 %0, %1;" : "=f"(x) : "f"(x));
    return x;
}
__device__ __forceinline__ u32 sptr(const void* p) {
    return (u32)__cvta_generic_to_shared(p);
}
__device__ __forceinline__ void ldsm4(u32& r0, u32& r1, u32& r2, u32& r3, u32 addr) {
    asm volatile("ldmatrix.sync.aligned.m8n8.x4.shared.b16 {%0,%1,%2,%3}, [%4];"
        : "=r"(r0), "=r"(r1), "=r"(r2), "=r"(r3) : "r"(addr));
}
__device__ __forceinline__ void ldsm4t(u32& r0, u32& r1, u32& r2, u32& r3, u32 addr) {
    asm volatile("ldmatrix.sync.aligned.m8n8.x4.trans.shared.b16 {%0,%1,%2,%3}, [%4];"
        : "=r"(r0), "=r"(r1), "=r"(r2), "=r"(r3) : "r"(addr));
}
__device__ __forceinline__ void mma16816(float* d, u32 a0, u32 a1, u32 a2,
                                         u32 a3, u32 b0, u32 b1) {
    asm volatile("mma.sync.aligned.m16n8k16.row.col.f32.f16.f16.f32 "
        "{%0,%1,%2,%3}, {%4,%5,%6,%7}, {%8,%9}, {%0,%1,%2,%3};"
        : "+f"(d[0]), "+f"(d[1]), "+f"(d[2]), "+f"(d[3])
        : "r"(a0), "r"(a1), "r"(a2), "r"(a3), "r"(b0), "r"(b1));
}

// ---------------- tf32 wmma GEMM body:  C = A(MxK) @ W(KxN) + bias ----------
// tf32 rna rounding at smem store; optional half output epilogue.
#define GT_ALD 36
#define GT_WLD 68
__device__ __forceinline__ void gemm_body(
    const float* __restrict__ A, const float* __restrict__ W,
    const float* __restrict__ bias, float* __restrict__ C,
    __half* __restrict__ Ch, float hscale,
    int M, int N, int K, int bm, int bn)
{
    __shared__ float As[128*GT_ALD];   // [m][k] k-chunk 32
    __shared__ float Ws[32*GT_WLD];    // [k][n]
    __shared__ float Bt[16*GT_WLD];    // bias tile (rows identical)
    __shared__ float scr[8][16*20];    // per-warp epilogue staging
    const int tid = threadIdx.x, w = tid >> 5, lane = tid & 31;
    const int wm = (w >> 1) * 32, wn = (w & 1) * 32;

    for (int i = tid; i < 16*64; i += 256) {
        int r = i >> 6, c = i & 63;
        Bt[r*GT_WLD + c] = bias[bn + c];
    }
    __syncthreads();

    wmma::fragment<wmma::accumulator, 16,16,8, float> acc[2][2];
    #pragma unroll
    for (int i = 0; i < 2; i++)
        #pragma unroll
        for (int j = 0; j < 2; j++)
            wmma::load_matrix_sync(acc[i][j], Bt + wn + j*16, GT_WLD, wmma::mem_row_major);

    for (int k0 = 0; k0 < K; k0 += 32) {
        #pragma unroll
        for (int i = 0; i < 4; i++) {
            int id = i*256 + tid;
            int row = id >> 3, kc = (id & 7) * 4;
            float4 v = *(const float4*)&A[(size_t)(bm + row) * K + k0 + kc];
            v.x = to_tf32(v.x); v.y = to_tf32(v.y);
            v.z = to_tf32(v.z); v.w = to_tf32(v.w);
            *(float4*)&As[row*GT_ALD + kc] = v;
        }
        #pragma unroll
        for (int i = 0; i < 2; i++) {
            int id = i*256 + tid;
            int kr = id >> 4, nc = (id & 15) * 4;
            float4 v = *(const float4*)&W[(size_t)(k0 + kr) * N + bn + nc];
            v.x = to_tf32(v.x); v.y = to_tf32(v.y);
            v.z = to_tf32(v.z); v.w = to_tf32(v.w);
            *(float4*)&Ws[kr*GT_WLD + nc] = v;
        }
        __syncthreads();
        #pragma unroll
        for (int ks = 0; ks < 4; ks++) {
            wmma::fragment<wmma::matrix_a, 16,16,8, wmma::precision::tf32, wmma::row_major> a0, a1;
            wmma::load_matrix_sync(a0, As + wm*GT_ALD + ks*8, GT_ALD);
            wmma::load_matrix_sync(a1, As + (wm+16)*GT_ALD + ks*8, GT_ALD);
            wmma::fragment<wmma::matrix_b, 16,16,8, wmma::precision::tf32, wmma::row_major> b0, b1;
            wmma::load_matrix_sync(b0, Ws + (ks*8)*GT_WLD + wn, GT_WLD);
            wmma::load_matrix_sync(b1, Ws + (ks*8)*GT_WLD + wn + 16, GT_WLD);
            wmma::mma_sync(acc[0][0], a0, b0, acc[0][0]);
            wmma::mma_sync(acc[0][1], a0, b1, acc[0][1]);
            wmma::mma_sync(acc[1][0], a1, b0, acc[1][0]);
            wmma::mma_sync(acc[1][1], a1, b1, acc[1][1]);
        }
        __syncthreads();
    }
    if (C) {
        #pragma unroll
        for (int i = 0; i < 2; i++)
            #pragma unroll
            for (int j = 0; j < 2; j++)
                wmma::store_matrix_sync(C + (size_t)(bm + wm + i*16) * N + bn + wn + j*16,
                                        acc[i][j], N, wmma::mem_row_major);
    }
    if (Ch) {
        const int erow = lane >> 1, ecol = (lane & 1) * 8;
        #pragma unroll
        for (int i = 0; i < 2; i++)
            #pragma unroll
            for (int j = 0; j < 2; j++) {
                wmma::store_matrix_sync(&scr[w][0], acc[i][j], 20, wmma::mem_row_major);
                __syncwarp();
                const float* p = &scr[w][erow*20 + ecol];
                __half2 hh[4];
                hh[0] = __floats2half2_rn(p[0]*hscale, p[1]*hscale);
                hh[1] = __floats2half2_rn(p[2]*hscale, p[3]*hscale);
                hh[2] = __floats2half2_rn(p[4]*hscale, p[5]*hscale);
                hh[3] = __floats2half2_rn(p[6]*hscale, p[7]*hscale);
                *(uint4*)&Ch[(size_t)(bm + wm + i*16 + erow) * N + bn + wn + j*16 + ecol] =
                    *(uint4*)hh;
                __syncwarp();
            }
    }
}

__global__ __launch_bounds__(256) void gemm_bias_tc(
    const float* __restrict__ A, const float* __restrict__ W,
    const float* __restrict__ bias, float* __restrict__ C, int M, int N, int K)
{
    gemm_body(A, W, bias, C, nullptr, 1.f, M, N, K, blockIdx.y * 128, blockIdx.x * 64);
}

// three projections in one launch (half outputs only); z selects (q,k,v)
__global__ __launch_bounds__(256) void gemm3_kernel(
    const float* q, const float* k, const float* v,
    const float* Wq, const float* Wk, const float* Wv,
    const float* bq, const float* bk, const float* bv)
{
    const float* A; const float* W; const float* bias; __half* Ch; float hs;
    if (blockIdx.z == 0)      { A = q; W = Wq; bias = bq; Ch = g_qph; hs = 0.125f; }
    else if (blockIdx.z == 1) { A = k; W = Wk; bias = bk; Ch = g_kph; hs = 1.f; }
    else                      { A = v; W = Wv; bias = bv; Ch = g_vph; hs = 1.f; }
    gemm_body(A, W, bias, nullptr, Ch, hs, B*S, D, D, blockIdx.y * 128, blockIdx.x * 64);
}

// ---------------- Wcoef transpose --------------------------------------------
__global__ void transw_kernel(const float* __restrict__ Wcoef)
{
    int i = blockIdx.x * 256 + threadIdx.x;          // 40960 total
    if (i < D*NB*H) {
        int n = i / (D*H), rem = i % (D*H);
        int d = rem / H, h = rem % H;
        g_wt[d*(NB*H) + n*H + h] = Wcoef[i];
    }
}

// ---------------- coef: (B*S x 512) @ (512 x 80), A read from half qph --------
__global__ void coef_kernel(const float* __restrict__ bcoef)
{
    __shared__ float qsm[16*33];
    __shared__ float wsm[32*80];
    const int bm = blockIdx.x * 16;
    const int t = threadIdx.x;
    const int r = t & 15;             // row within tile
    const int cg = t >> 4;            // col group: 5 cols each (16 groups)
    float acc[5] = {};
    for (int k0 = 0; k0 < D; k0 += 32) {
        #pragma unroll
        for (int i = 0; i < 2; i++) {
            int idx = i*256 + t;
            int rr = idx >> 5, cc = idx & 31;
            qsm[rr*33 + cc] = __half2float(g_qph[(size_t)(bm + rr) * D + k0 + cc]);
        }
        #pragma unroll
        for (int i = 0; i < 3; i++) {
            int idx = i*256 + t;
            if (idx < 640)
                *(float4*)&wsm[idx*4] = *(const float4*)&g_wt[k0*80 + idx*4];
        }
        __syncthreads();
        #pragma unroll 8
        for (int kk = 0; kk < 32; kk++) {
            float a = qsm[r*33 + kk];
            #pragma unroll
            for (int j = 0; j < 5; j++)
                acc[j] += a * wsm[kk*80 + cg*5 + j];
        }
        __syncthreads();
    }
    const int rg = bm + r;
    const int b = rg >> 11, s = rg & (S-1);
    #pragma unroll
    for (int j = 0; j < 5; j++) {
        int nh = cg*5 + j;
        int n = nh >> 3, h = nh & 7;
        float v = 8.f * acc[j] + bcoef[nh];          // undo the 0.125 in qph
        if (n == 1) v = fabsf(v);
        g_coef[(((size_t)n*B + b)*H + h)*S + s] = 0.0125f * v;   // 0.1 / sqrt(64)
    }
}

// ---------------- fused basis + QK^T (PTX mma) + exp + rowsum ----------------
// One head per block, 64q x 64k. Basis dot (half2 ladder) into mma C frags.
#define QK_LD 72
#define ET_LD 68
__global__ __launch_bounds__(256) void logits_kernel(const float* __restrict__ xdiff)
{
    __shared__ __half qs[64*QK_LD];
    __shared__ __half ks[64*QK_LD];

    const int bh = blockIdx.x, b = bh >> 3, h = bh & 7;
    const int k0 = blockIdx.y * 64, q0 = blockIdx.z * 64;
    const int tid = threadIdx.x;
    const int w = tid >> 5, lane = tid & 31;
    const int wr = w >> 1, wc = w & 1;        // 4x2 warps; warp tile 16q x 32k

    // tile loads (issue early; latency covered by basis compute below)
    for (int idx = tid; idx < 64*16; idx += 256) {
        int q = idx >> 4, c = (idx & 15) * 4;
        *(uint2*)&qs[q*QK_LD + c] =
            *(const uint2*)&g_qph[((size_t)b*S + q0 + q) * D + h*DH + c];
    }
    for (int idx = tid; idx < 64*16; idx += 256) {
        int k = idx >> 4, c = (idx & 15) * 4;
        *(uint2*)&ks[k*QK_LD + c] =
            *(const uint2*)&g_kph[((size_t)b*S + k0 + k) * D + h*DH + c];
    }

    // thread's cells per mma.m16n8k16 C layout:
    //   rows qr, qr+8 ; cols kc0 + j*8 + {0,1}, j = 0..3
    const int qr  = wr*16 + (lane >> 2);
    const int kc0 = wc*32 + (lane & 3)*2;

    float c[4][4];
    const half2 hm4 = __float2half2_rn(-4.f);
    const half2 h2c = __float2half2_rn(2.f);
    #pragma unroll
    for (int jr = 0; jr < 2; jr++) {
        const int row = qr + jr*8;
        half2 ch[10];
        #pragma unroll
        for (int n = 0; n < NB; n++) {
            float cv = __ldg(&g_coef[(((size_t)n*B + b)*H + h)*S + q0 + row]);
            if (n == 1) cv = -0.5f * cv;
            ch[n] = __float2half2_rn(cv);
        }
        const float* xrow = &xdiff[((size_t)b*S + q0 + row) * S + k0];
        #pragma unroll
        for (int j = 0; j < 4; j++) {
            float2 x2 = *(const float2*)&xrow[kc0 + j*8];
            float t0 = fmaf(-2.f, rintf(0.5f * x2.x), x2.x);
            float t1 = fmaf(-2.f, rintf(0.5f * x2.y), x2.y);
            float s0f, c0f, s1f, c1f;
            __sincosf(PI_F * t0, &s0f, &c0f);
            __sincosf(PI_F * t1, &s1f, &c1f);
            half2 X  = __floats2half2_rn(x2.x, x2.y);
            half2 s1 = __floats2half2_rn(s0f, s1f);
            half2 c1 = __floats2half2_rn(c0f, c1f);
            half2 t2 = __hfma2(__hmul2(s1, s1), hm4, h2c);   // 2*cos(2 pi x)
            half2 s3 = __hfma2(t2, s1, s1);
            half2 c3 = __hfma2(t2, c1, __hneg2(c1));
            half2 s5 = __hfma2(t2, s3, __hneg2(s1));
            half2 c5 = __hfma2(t2, c3, __hneg2(c1));
            half2 s7 = __hfma2(t2, s5, __hneg2(s3));
            half2 c7 = __hfma2(t2, c5, __hneg2(c3));
            half2 s9 = __hfma2(t2, s7, __hneg2(s5));
            half2 c9 = __hfma2(t2, c7, __hneg2(c5));
            half2 a = __hmul2(ch[0], X);
            a = __hfma2(ch[1], __hmul2(X, X), a);
            a = __hfma2(ch[2], s1, a);  a = __hfma2(ch[3], c1, a);
            a = __hfma2(ch[4], s3, a);  a = __hfma2(ch[5], c3, a);
            a = __hfma2(ch[6], s5, a);  a = __hfma2(ch[7], c5, a);
            a = __hfma2(ch[8], s9, a);  a = __hfma2(ch[9], c9, a);
            float2 f = __half22float2(a);
            c[j][jr*2 + 0] = f.x;
            c[j][jr*2 + 1] = f.y;
        }
    }
    __syncthreads();

    // mma: c += (0.125*Q) K^T   (fp16 inputs, fp32 accum)
    #pragma unroll
    for (int kk = 0; kk < 4; kk++) {
        u32 a0, a1, a2, a3;
        ldsm4(a0, a1, a2, a3,
              sptr(&qs[(wr*16 + (lane & 15))*QK_LD + kk*16 + (lane >> 4)*8]));
        #pragma unroll
        for (int jj = 0; jj < 2; jj++) {
            u32 b0, b1, b2, b3;
            ldsm4(b0, b1, b2, b3,
                  sptr(&ks[(wc*32 + jj*16 + (lane & 7) + ((lane >> 4) & 1)*8)*QK_LD
                           + kk*16 + ((lane >> 3) & 1)*8]));
            mma16816(c[jj*2],     a0, a1, a2, a3, b0, b1);
            mma16816(c[jj*2 + 1], a0, a1, a2, a3, b2, b3);
        }
    }

    // exp in registers + row partial sums
    float s0 = 0.f, s1 = 0.f;
    #pragma unroll
    for (int j = 0; j < 4; j++) {
        c[j][0] = __expf(c[j][0]); c[j][1] = __expf(c[j][1]);
        c[j][2] = __expf(c[j][2]); c[j][3] = __expf(c[j][3]);
        s0 += c[j][0] + c[j][1];
        s1 += c[j][2] + c[j][3];
    }
    s0 += __shfl_xor_sync(0xffffffffu, s0, 1);
    s0 += __shfl_xor_sync(0xffffffffu, s0, 2);
    s1 += __shfl_xor_sync(0xffffffffu, s1, 1);
    s1 += __shfl_xor_sync(0xffffffffu, s1, 2);
    if ((lane & 3) == 0) {
        atomicAdd(&g_rowsum[(size_t)bh*S + q0 + qr],     s0);
        atomicAdd(&g_rowsum[(size_t)bh*S + q0 + qr + 8], s1);
    }

    __syncthreads();              // all warps done reading qs
    __half* et = qs;              // reuse qs as 64 x ET_LD half staging
    #pragma unroll
    for (int j = 0; j < 4; j++) {
        int kc = kc0 + j*8;
        *(__half2*)&et[qr*ET_LD + kc]       = __floats2half2_rn(c[j][0], c[j][1]);
        *(__half2*)&et[(qr + 8)*ET_LD + kc] = __floats2half2_rn(c[j][2], c[j][3]);
    }
    __syncthreads();

    // coalesced e store
    for (int idx = tid; idx < 64*16; idx += 256) {
        int row = idx >> 4, c4 = (idx & 15) * 4;
        *(uint2*)&g_e[((size_t)bh*S + q0 + row) * S + k0 + c4] =
            *(const uint2*)&et[row*ET_LD + c4];
    }
}

// ---------------- fused normalize + PV (PTX mma, smem-staged raw e) ----------
#define PT_LD 72
#define VT_LD 72
__global__ __launch_bounds__(256) void softpv_kernel(float* __restrict__ attn)
{
    __shared__ __half pt[64*PT_LD];
    __shared__ __half vt[64*VT_LD];
    const int b = blockIdx.z, h = blockIdx.y;
    const int q0 = blockIdx.x * 64;
    const int tid = threadIdx.x;
    const int w = tid >> 5, lane = tid & 31;
    const int wr = w >> 1, wc = w & 1;        // 4x2 warps: 16q x 32d each
    const int r  = tid >> 2, tq = tid & 3;    // attn write: 64 rows x 4 threads

    const size_t rowbase = ((size_t)(b*H + h)*S + q0) * S;
    float* arow = attn + rowbase + (size_t)r * S;
    const float riz_r = 1.f / g_rowsum[(size_t)(b*H + h)*S + q0 + r];

    const int qr = wr*16 + (lane >> 2);
    const float riz0 = 1.f / g_rowsum[(size_t)(b*H + h)*S + q0 + qr];
    const float riz1 = 1.f / g_rowsum[(size_t)(b*H + h)*S + q0 + qr + 8];

    float c[4][4] = {};

    for (int k0 = 0; k0 < S; k0 += 64) {
        // raw e tile (64q x 64k), straight half copy
        #pragma unroll
        for (int i = 0; i < 4; i++) {
            int idx = i*256 + tid;                    // uint2 (4 halves) units
            int row = idx >> 4, cc = (idx & 15) * 4;
            *(uint2*)&pt[row*PT_LD + cc] =
                *(const uint2*)&g_e[rowbase + (size_t)row * S + k0 + cc];
        }
        // V tile (64k x 64d)
        #pragma unroll
        for (int i = 0; i < 4; i++) {
            int idx = i*256 + tid;
            int k = idx >> 4, cc = (idx & 15) * 4;
            *(uint2*)&vt[k*VT_LD + cc] =
                *(const uint2*)&g_vph[((size_t)b*S + k0 + k)*D + h*DH + cc];
        }
        __syncthreads();
        // attn write from smem: e * riz
        #pragma unroll
        for (int j = 0; j < 4; j++) {
            __half2 e0 = *(const __half2*)&pt[r*PT_LD + tq*16 + j*4];
            __half2 e1 = *(const __half2*)&pt[r*PT_LD + tq*16 + j*4 + 2];
            float2 f0 = __half22float2(e0), f1 = __half22float2(e1);
            *(float4*)&arow[k0 + tq*16 + j*4] =
                make_float4(f0.x*riz_r, f0.y*riz_r, f1.x*riz_r, f1.y*riz_r);
        }
        // mma over 4 k-chunks of 16: A = raw e (ldsm), B = V^T (ldsm trans)
        #pragma unroll
        for (int kk = 0; kk < 4; kk++) {
            u32 a0, a1, a2, a3;
            ldsm4(a0, a1, a2, a3,
                  sptr(&pt[(wr*16 + (lane & 15))*PT_LD + kk*16 + (lane >> 4)*8]));
            #pragma unroll
            for (int jj = 0; jj < 2; jj++) {
                u32 b0, b1, b2, b3;
                ldsm4t(b0, b1, b2, b3,
                       sptr(&vt[(kk*16 + (lane & 15))*VT_LD + wc*32 + jj*16
                                + ((lane >> 4) << 3)]));
                mma16816(c[jj*2],     a0, a1, a2, a3, b0, b1);
                mma16816(c[jj*2 + 1], a0, a1, a2, a3, b2, b3);
            }
        }
        __syncthreads();
    }

    // scale by 1/rowsum and store
    #pragma unroll
    for (int j = 0; j < 4; j++) {
        int col = h*DH + wc*32 + j*8 + (lane & 3)*2;
        *(float2*)&g_attnv[((size_t)b*S + q0 + qr)*D + col] =
            make_float2(c[j][0]*riz0, c[j][1]*riz0);
        *(float2*)&g_attnv[((size_t)b*S + q0 + qr + 8)*D + col] =
            make_float2(c[j][2]*riz1, c[j][3]*riz1);
    }
}

// -----------------------------------------------------------------------------
extern "C" void kernel_launch(void* const* d_in, const int* in_sizes, int n_in,
                              void* d_out, int out_size)
{
    const float* q     = (const float*)d_in[0];
    const float* k     = (const float*)d_in[1];
    const float* v     = (const float*)d_in[2];
    const float* xdiff = (const float*)d_in[3];
    const float* Wq    = (const float*)d_in[4];
    const float* bq    = (const float*)d_in[5];
    const float* Wk    = (const float*)d_in[6];
    const float* bk    = (const float*)d_in[7];
    const float* Wv    = (const float*)d_in[8];
    const float* bv    = (const float*)d_in[9];
    const float* Wcoef = (const float*)d_in[10];
    const float* bcoef = (const float*)d_in[11];
    const float* Wo    = (const float*)d_in[12];
    const float* bo    = (const float*)d_in[13];
    float* out = (float*)d_out;                       // [B*S*D] out | [B*H*S*S] attn
    float* attn = out + (size_t)B*S*D;

    float *av, *rs;
    cudaGetSymbolAddress((void**)&av, g_attnv);
    cudaGetSymbolAddress((void**)&rs, g_rowsum);

    cudaMemsetAsync(rs, 0, (size_t)B*H*S*sizeof(float), 0);

    gemm3_kernel<<<dim3(D/64, (B*S)/128, 3), 256>>>(q, k, v, Wq, Wk, Wv, bq, bk, bv);

    transw_kernel<<<(D*NB*H + 255)/256, 256>>>(Wcoef);
    coef_kernel<<<(B*S)/16, 256>>>(bcoef);

    logits_kernel<<<dim3(B*H, S/64, S/64), 256>>>(xdiff);

    softpv_kernel<<<dim3(S/64, H, B), 256>>>(attn);

    gemm_bias_tc<<<dim3(D/64, (B*S)/128), 256>>>(av, Wo, bo, out, B*S, D, D);
}